// round 9
// baseline (speedup 1.0000x reference)
#include <cuda_runtime.h>

#define BN 256
#define NN 1000
#define DD 128
#define NC 8
#define CR 125
#define NEGV (-1e9f)
typedef unsigned long long u64;

// -------- device scratch (sanctioned: __device__ globals) --------
__device__ float g_mpart[BN * NC * DD];     // partial means
__device__ float g_qt[BN * DD * 8];         // qtilde [b][d][h]
__device__ float g_cp[(size_t)BN * NN * 8]; // compat -> attn, [b][n][h]
__device__ float g_ebp[BN * NC * 1024];     // ebar partials
__device__ float g_gt[BN * DD];             // gtilde
__device__ float g_lg[BN * NN];             // logits
__device__ float g_lmax[BN * NC];           // per-chunk logit max

static __device__ __forceinline__ u64 pack2(float a, float b) {
    u64 r; asm("mov.b64 %0, {%1, %2};" : "=l"(r) : "f"(a), "f"(b)); return r;
}
static __device__ __forceinline__ u64 packdup(float a) { return pack2(a, a); }
static __device__ __forceinline__ u64 fma2(u64 a, u64 b, u64 c) {
    u64 d; asm("fma.rn.f32x2 %0, %1, %2, %3;" : "=l"(d) : "l"(a), "l"(b), "l"(c)); return d;
}
static __device__ __forceinline__ u64 add2(u64 a, u64 b) {
    u64 d; asm("add.rn.f32x2 %0, %1, %2;" : "=l"(d) : "l"(a), "l"(b)); return d;
}
static __device__ __forceinline__ float2 unpack2(u64 v) {
    float lo, hi; asm("mov.b64 {%0, %1}, %2;" : "=f"(lo), "=f"(hi) : "l"(v));
    return make_float2(lo, hi);
}
static __device__ __forceinline__ u64 shflx2(u64 v, int m) {
    float2 f = unpack2(v);
    f.x = __shfl_xor_sync(0xffffffffu, f.x, m);
    f.y = __shfl_xor_sync(0xffffffffu, f.y, m);
    return pack2(f.x, f.y);
}
static __device__ __forceinline__ float tanh_fast(float x) {
    float y; asm("tanh.approx.f32 %0, %1;" : "=f"(y) : "f"(x)); return y;
}

// ---- K1: partial means, grid (B*NC) ----
__global__ __launch_bounds__(256) void kmean(const float* __restrict__ emb) {
    __shared__ float s[256];
    int bx = blockIdx.x, b = bx >> 3, c = bx & 7;
    int t = threadIdx.x, d = t & 127, g = t >> 7;
    const float* E = emb + ((size_t)b * NN + c * CR) * DD + d;
    float a0 = 0, a1 = 0, a2 = 0, a3 = 0;
    int n = g;
    for (; n + 6 < CR; n += 8) {
        a0 += E[(size_t)n * DD];       a1 += E[(size_t)(n + 2) * DD];
        a2 += E[(size_t)(n + 4) * DD]; a3 += E[(size_t)(n + 6) * DD];
    }
    for (; n < CR; n += 2) a0 += E[(size_t)n * DD];
    s[t] = (a0 + a1) + (a2 + a3);
    __syncthreads();
    if (t < 128) g_mpart[bx * DD + t] = s[t] + s[128 + t];
}

// ---- K2: q + qtilde per batch, grid B ----
__global__ __launch_bounds__(128) void kprep(const float* __restrict__ emb,
    const float* __restrict__ Wf, const float* __restrict__ Ws,
    const float* __restrict__ Wn, const int* __restrict__ fidx,
    const int* __restrict__ lidx) {
    __shared__ float s_mean[128], s_ef[128], s_el[128], s_q[128];
    int b = blockIdx.x, t = threadIdx.x;
    float m = 0;
    #pragma unroll
    for (int c = 0; c < 8; c++) m += g_mpart[(b * 8 + c) * DD + t];
    s_mean[t] = m * (1.0f / NN);
    s_ef[t] = emb[((size_t)b * NN + fidx[b]) * DD + t];
    s_el[t] = emb[((size_t)b * NN + lidx[b]) * DD + t];
    __syncthreads();
    float acc = 0;
    #pragma unroll 4
    for (int i = 0; i < DD; i++) acc += s_mean[i] * Wf[i * DD + t];
    #pragma unroll 4
    for (int i = 0; i < DD; i++) acc += s_ef[i] * Ws[i * DD + t];
    #pragma unroll 4
    for (int i = 0; i < DD; i++) acc += s_el[i] * Ws[(DD + i) * DD + t];
    s_q[t] = acc;
    __syncthreads();
    float o[8];
    #pragma unroll
    for (int h = 0; h < 8; h++) {
        const float* w = Wn + t * 384 + h * 16;
        const float* qq = s_q + h * 16;
        float a = 0;
        #pragma unroll
        for (int k = 0; k < 16; k++) a += w[k] * qq[k];
        o[h] = a * 0.25f;
    }
    float4* dst = (float4*)(g_qt + (b * DD + t) * 8);
    dst[0] = make_float4(o[0], o[1], o[2], o[3]);
    dst[1] = make_float4(o[4], o[5], o[6], o[7]);
}

// ---- K3: compat, grid (B*NC), 8 lanes per row, uniform trip count ----
__global__ __launch_bounds__(256) void kcompat(const float* __restrict__ emb) {
    __shared__ float s_qt[1024];
    int bx = blockIdx.x, b = bx >> 3, c = bx & 7;
    int t = threadIdx.x;
    *(float4*)(s_qt + t * 4) = *(const float4*)(g_qt + b * 1024 + t * 4);
    __syncthreads();
    int r = t >> 3, s = t & 7;
    #pragma unroll
    for (int it = 0; it < 4; it++) {
        int rr = r + 32 * it;
        bool valid = rr < CR;
        int rcl = valid ? rr : (CR - 1);
        size_t row = (size_t)b * NN + c * CR + rcl;
        const float4* ep = (const float4*)(emb + row * DD);
        u64 acc0 = 0, acc1 = 0, acc2 = 0, acc3 = 0;
        #pragma unroll
        for (int j = 0; j < 4; j++) {
            float4 e = ep[s + 8 * j];
            const u64* qp = (const u64*)s_qt + (s + 8 * j) * 16;
            u64 ex = packdup(e.x), ey = packdup(e.y), ez = packdup(e.z), ew = packdup(e.w);
            acc0 = fma2(ex, qp[0], acc0);  acc1 = fma2(ex, qp[1], acc1);
            acc2 = fma2(ex, qp[2], acc2);  acc3 = fma2(ex, qp[3], acc3);
            acc0 = fma2(ey, qp[4], acc0);  acc1 = fma2(ey, qp[5], acc1);
            acc2 = fma2(ey, qp[6], acc2);  acc3 = fma2(ey, qp[7], acc3);
            acc0 = fma2(ez, qp[8], acc0);  acc1 = fma2(ez, qp[9], acc1);
            acc2 = fma2(ez, qp[10], acc2); acc3 = fma2(ez, qp[11], acc3);
            acc0 = fma2(ew, qp[12], acc0); acc1 = fma2(ew, qp[13], acc1);
            acc2 = fma2(ew, qp[14], acc2); acc3 = fma2(ew, qp[15], acc3);
        }
        // butterfly over the 8 lanes sharing this row (all lanes participate)
        u64 s0 = (s & 1) ? acc0 : acc2;
        u64 s1 = (s & 1) ? acc1 : acc3;
        u64 g0 = shflx2(s0, 1), g1 = shflx2(s1, 1);
        u64 v0 = add2((s & 1) ? acc2 : acc0, g0);
        u64 v1 = add2((s & 1) ? acc3 : acc1, g1);
        u64 s2 = (s & 2) ? v0 : v1;
        u64 g2 = shflx2(s2, 2);
        u64 w = add2((s & 2) ? v1 : v0, g2);
        w = add2(w, shflx2(w, 4));
        if (valid && s < 4) {
            int p = (s & 1) * 2 + ((s >> 1) & 1);
            float2 f = unpack2(w);
            *(float2*)(g_cp + row * 8 + 2 * p) = f;
        }
    }
}

// ---- K4: per-head softmax (in place), grid B ----
__global__ __launch_bounds__(512) void kattn(const int* __restrict__ mask) {
    __shared__ float s_c[NN * 9];
    __shared__ float s_m[8], s_i[8], s_red[32];
    int b = blockIdx.x, t = threadIdx.x, lane = t & 31, warp = t >> 5;
    float* cp = g_cp + (size_t)b * NN * 8;
    const int* mk = mask + (size_t)b * NN;
    for (int i = t; i < NN * 8; i += 512) {
        int n = i >> 3, h = i & 7;
        float v = cp[i];
        if (mk[n]) v = -1e30f;
        s_c[n * 9 + h] = v;
    }
    __syncthreads();
    int h = warp >> 1, seg = warp & 1;
    float mx = -1e30f;
    for (int n = seg * 32 + lane; n < NN; n += 64) mx = fmaxf(mx, s_c[n * 9 + h]);
    #pragma unroll
    for (int o = 16; o > 0; o >>= 1) mx = fmaxf(mx, __shfl_xor_sync(~0u, mx, o));
    if (lane == 0) s_red[warp] = mx;
    __syncthreads();
    float hm = fmaxf(s_red[2 * h], s_red[2 * h + 1]);
    float sm = 0;
    for (int n = seg * 32 + lane; n < NN; n += 64) sm += __expf(s_c[n * 9 + h] - hm);
    #pragma unroll
    for (int o = 16; o > 0; o >>= 1) sm += __shfl_xor_sync(~0u, sm, o);
    if (lane == 0) s_red[16 + warp] = sm;
    __syncthreads();
    if (t < 8) {
        s_m[t] = fmaxf(s_red[2 * t], s_red[2 * t + 1]);
        s_i[t] = 1.0f / (s_red[16 + 2 * t] + s_red[16 + 2 * t + 1]);
    }
    __syncthreads();
    for (int i = t; i < NN * 8; i += 512) {
        int n = i >> 3, hh = i & 7;
        cp[i] = __expf(s_c[n * 9 + hh] - s_m[hh]) * s_i[hh];
    }
}

// ---- K5: ebar partials, grid (B*NC) ----
__global__ __launch_bounds__(256) void kebar(const float* __restrict__ emb) {
    __shared__ float s_at[CR * 8];
    __shared__ float s_p[2048];
    int bx = blockIdx.x, b = bx >> 3, c = bx & 7;
    int t = threadIdx.x, d = t & 127, g = t >> 7;
    const float* cp = g_cp + ((size_t)b * NN + c * CR) * 8;
    for (int i = t; i < CR * 8; i += 256) s_at[i] = cp[i];
    __syncthreads();
    const float* E = emb + ((size_t)b * NN + c * CR) * DD + d;
    u64 a0 = 0, a1 = 0, a2 = 0, a3 = 0;
    int n = g;
    for (; n + 6 < CR; n += 8) {
        float e0 = E[(size_t)n * DD],       e1 = E[(size_t)(n + 2) * DD];
        float e2 = E[(size_t)(n + 4) * DD], e3 = E[(size_t)(n + 6) * DD];
        const u64* t0 = (const u64*)(s_at + n * 8);
        const u64* t1 = (const u64*)(s_at + (n + 2) * 8);
        const u64* t2 = (const u64*)(s_at + (n + 4) * 8);
        const u64* t3 = (const u64*)(s_at + (n + 6) * 8);
        u64 d0 = packdup(e0), d1 = packdup(e1), d2 = packdup(e2), d3 = packdup(e3);
        a0 = fma2(d0, t0[0], a0); a1 = fma2(d0, t0[1], a1);
        a2 = fma2(d0, t0[2], a2); a3 = fma2(d0, t0[3], a3);
        a0 = fma2(d1, t1[0], a0); a1 = fma2(d1, t1[1], a1);
        a2 = fma2(d1, t1[2], a2); a3 = fma2(d1, t1[3], a3);
        a0 = fma2(d2, t2[0], a0); a1 = fma2(d2, t2[1], a1);
        a2 = fma2(d2, t2[2], a2); a3 = fma2(d2, t2[3], a3);
        a0 = fma2(d3, t3[0], a0); a1 = fma2(d3, t3[1], a1);
        a2 = fma2(d3, t3[2], a2); a3 = fma2(d3, t3[3], a3);
    }
    for (; n < CR; n += 2) {
        u64 ed = packdup(E[(size_t)n * DD]);
        const u64* at = (const u64*)(s_at + n * 8);
        a0 = fma2(ed, at[0], a0); a1 = fma2(ed, at[1], a1);
        a2 = fma2(ed, at[2], a2); a3 = fma2(ed, at[3], a3);
    }
    float2 f0 = unpack2(a0), f1 = unpack2(a1), f2 = unpack2(a2), f3 = unpack2(a3);
    float* pp = s_p + g * 1024 + d;
    pp[0] = f0.x; pp[128] = f0.y; pp[256] = f1.x; pp[384] = f1.y;
    pp[512] = f2.x; pp[640] = f2.y; pp[768] = f3.x; pp[896] = f3.y;
    __syncthreads();
    for (int i = t; i < 1024; i += 256)
        g_ebp[bx * 1024 + i] = s_p[i] + s_p[1024 + i];
}

// ---- K6: ebar reduce + heads -> glimpse -> gtilde, grid B ----
__global__ __launch_bounds__(128) void kglimpse(const float* __restrict__ Wn,
                                                const float* __restrict__ Wo) {
    __shared__ float s_eb[1024], s_h[128], s_gl[128];
    int b = blockIdx.x, t = threadIdx.x;
    for (int i = t; i < 1024; i += 128) {
        float a = 0;
        #pragma unroll
        for (int c = 0; c < 8; c++) a += g_ebp[(b * 8 + c) * 1024 + i];
        s_eb[i] = a;
    }
    __syncthreads();
    {
        int h = t >> 4;
        const float* eb = s_eb + h * 128;
        float a = 0;
        #pragma unroll 4
        for (int d = 0; d < 128; d++) a += eb[d] * Wn[d * 384 + 128 + t];
        s_h[t] = a;
    }
    __syncthreads();
    {
        float a = 0;
        #pragma unroll 4
        for (int i = 0; i < 128; i++) a += s_h[i] * Wo[i * 128 + t];
        s_gl[t] = a;
    }
    __syncthreads();
    {
        const float* w = Wn + t * 384 + 256;
        float a = 0;
        #pragma unroll 4
        for (int j = 0; j < 128; j++) a += w[j] * s_gl[j];
        g_gt[b * 128 + t] = a * 0.08838834764831845f;
    }
}

// ---- K7: logits + per-chunk max, grid (B*NC), uniform trip count ----
__global__ __launch_bounds__(256) void klogits(const float* __restrict__ emb,
                                               const int* __restrict__ mask) {
    __shared__ float s_gt[128];
    __shared__ float s_red[8];
    int bx = blockIdx.x, b = bx >> 3, c = bx & 7;
    int t = threadIdx.x, lane = t & 31, warp = t >> 5;
    if (t < 128) s_gt[t] = g_gt[b * DD + t];
    __syncthreads();
    int r = t >> 3, s = t & 7;
    float lm = -1e30f;
    #pragma unroll
    for (int it = 0; it < 4; it++) {
        int rr = r + 32 * it;
        bool valid = rr < CR;
        int rcl = valid ? rr : (CR - 1);
        size_t row = (size_t)b * NN + c * CR + rcl;
        const float4* ep = (const float4*)(emb + row * DD);
        u64 acc = 0;
        #pragma unroll
        for (int j = 0; j < 4; j++) {
            float4 e = ep[s + 8 * j];
            const u64* gp = (const u64*)s_gt + (s + 8 * j) * 2;
            acc = fma2(pack2(e.x, e.y), gp[0], acc);
            acc = fma2(pack2(e.z, e.w), gp[1], acc);
        }
        float2 v = unpack2(acc);
        float f = v.x + v.y;
        f += __shfl_xor_sync(~0u, f, 1);
        f += __shfl_xor_sync(~0u, f, 2);
        f += __shfl_xor_sync(~0u, f, 4);
        if (valid && s == 0) {
            float vv = tanh_fast(f) * 10.0f;
            if (mask[row]) vv = NEGV;
            g_lg[row] = vv;
            lm = fmaxf(lm, vv);
        }
    }
    #pragma unroll
    for (int o = 16; o > 0; o >>= 1) lm = fmaxf(lm, __shfl_xor_sync(~0u, lm, o));
    if (lane == 0) s_red[warp] = lm;
    __syncthreads();
    if (t == 0) {
        float m = -1e30f;
        #pragma unroll
        for (int w = 0; w < 8; w++) m = fmaxf(m, s_red[w]);
        g_lmax[bx] = m;
    }
}

// ---- K8: log-softmax, grid B ----
__global__ __launch_bounds__(256) void kfinal(float* __restrict__ out) {
    __shared__ float s_red[8];
    __shared__ float s_lz;
    int b = blockIdx.x, t = threadIdx.x, lane = t & 31, warp = t >> 5;
    float bmax = -1e30f;
    #pragma unroll
    for (int c = 0; c < 8; c++) bmax = fmaxf(bmax, g_lmax[b * 8 + c]);
    const float* lg = g_lg + (size_t)b * NN;
    float s = 0;
    for (int n = t; n < NN; n += 256) s += __expf(lg[n] - bmax);
    #pragma unroll
    for (int o = 16; o > 0; o >>= 1) s += __shfl_xor_sync(~0u, s, o);
    if (lane == 0) s_red[warp] = s;
    __syncthreads();
    if (t == 0) {
        float tot = 0;
        #pragma unroll
        for (int w = 0; w < 8; w++) tot += s_red[w];
        s_lz = bmax + logf(tot);
    }
    __syncthreads();
    float logZ = s_lz;
    float* ob = out + (size_t)b * NN;
    for (int n = t; n < NN; n += 256) ob[n] = lg[n] - logZ;
}

extern "C" void kernel_launch(void* const* d_in, const int* in_sizes, int n_in,
                              void* d_out, int out_size) {
    const float* emb = (const float*)d_in[0];
    const float* Wn  = (const float*)d_in[1];
    const float* Wf  = (const float*)d_in[2];
    const float* Ws  = (const float*)d_in[3];
    const float* Wo  = (const float*)d_in[4];
    const int* fidx  = (const int*)d_in[5];
    const int* lidx  = (const int*)d_in[6];
    const int* mask  = (const int*)d_in[7];
    float* out = (float*)d_out;

    kmean<<<BN * NC, 256>>>(emb);
    kprep<<<BN, 128>>>(emb, Wf, Ws, Wn, fidx, lidx);
    kcompat<<<BN * NC, 256>>>(emb);
    kattn<<<BN, 512>>>(mask);
    kebar<<<BN * NC, 256>>>(emb);
    kglimpse<<<BN, 128>>>(Wn, Wo);
    klogits<<<BN * NC, 256>>>(emb, mask);
    kfinal<<<BN, 256>>>(out);
}

// round 10
// speedup vs baseline: 1.5821x; 1.5821x over previous
#include <cuda_runtime.h>
#include <cuda_fp16.h>

#define NN 1000
#define DD 128
#define NEGV (-1e9f)
typedef unsigned long long u64;
typedef unsigned int u32;

// fp16 copy of embeddings, written by phase 0, read by phases 1/2/3
__device__ __align__(16) __half2 g_e16[(size_t)256 * NN * 64];

static __device__ __forceinline__ u64 pack2(float a, float b) {
    u64 r; asm("mov.b64 %0, {%1, %2};" : "=l"(r) : "f"(a), "f"(b)); return r;
}
static __device__ __forceinline__ u64 packdup(float a) { return pack2(a, a); }
static __device__ __forceinline__ u64 fma2(u64 a, u64 b, u64 c) {
    u64 d; asm("fma.rn.f32x2 %0, %1, %2, %3;" : "=l"(d) : "l"(a), "l"(b), "l"(c)); return d;
}
static __device__ __forceinline__ float2 unpack2(u64 v) {
    float lo, hi; asm("mov.b64 {%0, %1}, %2;" : "=f"(lo), "=f"(hi) : "l"(v));
    return make_float2(lo, hi);
}
static __device__ __forceinline__ float tanh_fast(float x) {
    float y; asm("tanh.approx.f32 %0, %1;" : "=f"(y) : "f"(x)); return y;
}
static __device__ __forceinline__ float2 h2f(u32 w) {
    return __half22float2(*(__half2*)&w);
}

// smem word offsets (same footprint as v4: 80768 bytes)
#define O_COMPAT 0          // 8000 (phase0 partials 1024 / phase2 partials 4096 / s_lg)
#define O_BUF    8000       // 9216 : stage buffer 256 rows x 9 uint4 (36KB); also s_at
#define O_QT     17216      // 1024 = qt[d][8]
#define O_MEAN   18240
#define O_Q      18368
#define O_EF     18496
#define O_EL     18624
#define O_HEADS  18752
#define O_GL     18880
#define O_GT     19008
#define O_EBAR   19136      // 1024
#define O_RED    20160      // 32
#define SM_WORDS 20192

__global__ __launch_bounds__(512, 2) void attn_v7(
    const float* __restrict__ emb, const float* __restrict__ Wn,
    const float* __restrict__ Wf, const float* __restrict__ Ws,
    const float* __restrict__ Wo, const int* __restrict__ fidx,
    const int* __restrict__ lidx, const int* __restrict__ mask,
    float* __restrict__ out)
{
    extern __shared__ float sm[];
    float* s_compat = sm + O_COMPAT;
    float* s_buf    = sm + O_BUF;
    float* s_QT     = sm + O_QT;
    float* s_mean   = sm + O_MEAN;
    float* s_q      = sm + O_Q;
    float* s_ef     = sm + O_EF;
    float* s_el     = sm + O_EL;
    float* s_heads  = sm + O_HEADS;
    float* s_gl     = sm + O_GL;
    float* s_gt     = sm + O_GT;
    float* s_ebar   = sm + O_EBAR;
    float* s_red    = sm + O_RED;

    const int b = blockIdx.x, t = threadIdx.x;
    const int lane = t & 31, warp = t >> 5;
    const float* embB = emb + (size_t)b * NN * DD;
    const int* mkB = mask + (size_t)b * NN;
    __half2* e16B = g_e16 + (size_t)b * (NN * 64);

    // chunk idx: T = idx>>1 (256 rows), c = idx&1 (64-dim half). 8 chunks total.
    uint4 pr[4];
    auto ld16 = [&](int idx) {
        int T = idx >> 1, c = idx & 1;
        const uint4* src = (const uint4*)e16B;
        #pragma unroll
        for (int k = 0; k < 4; k++) {
            int i = (k << 9) + t;
            int rl = i >> 3, seg = i & 7;
            int gr = T * 256 + rl; if (gr > NN - 1) gr = NN - 1;
            pr[k] = src[(size_t)gr * 16 + c * 8 + seg];
        }
    };
    auto st16 = [&]() {
        #pragma unroll
        for (int k = 0; k < 4; k++) {
            int i = (k << 9) + t;
            int rl = i >> 3, seg = i & 7;
            ((uint4*)s_buf)[rl * 9 + seg] = pr[k];
        }
    };

    // ---- Phase 0: mean + fp16 conversion (each thread: dim-pair p, rows g+8k) ----
    {
        int p = t & 63, g = t >> 6;
        const float2* E2 = (const float2*)embB + p;
        __half2* O = e16B + p;
        float ax = 0, ay = 0, bx = 0, by = 0;
        int n = g;
        for (; n + 24 < NN; n += 32) {
            float2 v0 = E2[(size_t)n * 64];
            float2 v1 = E2[(size_t)(n + 8) * 64];
            float2 v2 = E2[(size_t)(n + 16) * 64];
            float2 v3 = E2[(size_t)(n + 24) * 64];
            O[(size_t)n * 64]        = __floats2half2_rn(v0.x, v0.y);
            O[(size_t)(n + 8) * 64]  = __floats2half2_rn(v1.x, v1.y);
            O[(size_t)(n + 16) * 64] = __floats2half2_rn(v2.x, v2.y);
            O[(size_t)(n + 24) * 64] = __floats2half2_rn(v3.x, v3.y);
            ax += v0.x; ay += v0.y; bx += v1.x; by += v1.y;
            ax += v2.x; ay += v2.y; bx += v3.x; by += v3.y;
        }
        for (; n < NN; n += 8) {
            float2 v = E2[(size_t)n * 64];
            O[(size_t)n * 64] = __floats2half2_rn(v.x, v.y);
            ax += v.x; ay += v.y;
        }
        s_compat[g * 128 + 2 * p]     = ax + bx;
        s_compat[g * 128 + 2 * p + 1] = ay + by;
    }
    if (t < DD)       s_ef[t] = embB[(size_t)fidx[b] * DD + t];
    else if (t < 256) s_el[t - DD] = embB[(size_t)lidx[b] * DD + (t - DD)];
    __syncthreads();
    if (t < DD) {
        float m = 0;
        #pragma unroll
        for (int g = 0; g < 8; g++) m += s_compat[g * 128 + t];
        s_mean[t] = m * (1.0f / NN);
    }
    __syncthreads();

    // ---- Phase 0b: q = mean@Wf + [ef;el]@Ws ----
    if (t < DD) {
        float acc = 0.f;
        #pragma unroll 4
        for (int i = 0; i < DD; i++) acc += s_mean[i] * Wf[i * DD + t];
        #pragma unroll 4
        for (int i = 0; i < DD; i++) acc += s_ef[i] * Ws[i * DD + t];
        #pragma unroll 4
        for (int i = 0; i < DD; i++) acc += s_el[i] * Ws[(DD + i) * DD + t];
        s_q[t] = acc;
    }
    __syncthreads();

    // ---- Phase 0c: qt[d][h] ----
    if (t < 256) {
        int d = t >> 1, h0 = (t & 1) * 4;
        #pragma unroll
        for (int h = h0; h < h0 + 4; h++) {
            const float* w = Wn + d * 384 + h * 16;
            const float* qq = s_q + h * 16;
            float acc = 0.f;
            #pragma unroll
            for (int k = 0; k < 16; k++) acc += w[k] * qq[k];
            s_QT[d * 8 + h] = acc * 0.25f;
        }
    }
    // first stage of phase 1 (g_e16 visible after the barrier inside phase-1 loop;
    // writes were by this block, ordered by the __syncthreads above)
    ld16(0);

    // ---- Phase 1: compat from fp16, 8 chunk-iters, 2 thr/row x 4 heads ----
    {
        const int r = t >> 1, q4 = t & 1;
        const ulonglong2* qt2 = (const ulonglong2*)s_QT + q4;
        u64 acc01 = 0, acc23 = 0;
        for (int idx = 0; idx < 8; idx++) {
            __syncthreads();
            st16();
            __syncthreads();
            if (idx < 7) ld16(idx + 1);
            const uint4* bp = (const uint4*)s_buf + r * 9;
            int c = idx & 1;
            #pragma unroll
            for (int j = 0; j < 8; j++) {
                uint4 e = bp[j];
                int db = c * 64 + j * 8;
                float2 f; ulonglong2 qa;
                f = h2f(e.x);
                qa = qt2[2*(db+0)]; acc01 = fma2(packdup(f.x), qa.x, acc01); acc23 = fma2(packdup(f.x), qa.y, acc23);
                qa = qt2[2*(db+1)]; acc01 = fma2(packdup(f.y), qa.x, acc01); acc23 = fma2(packdup(f.y), qa.y, acc23);
                f = h2f(e.y);
                qa = qt2[2*(db+2)]; acc01 = fma2(packdup(f.x), qa.x, acc01); acc23 = fma2(packdup(f.x), qa.y, acc23);
                qa = qt2[2*(db+3)]; acc01 = fma2(packdup(f.y), qa.x, acc01); acc23 = fma2(packdup(f.y), qa.y, acc23);
                f = h2f(e.z);
                qa = qt2[2*(db+4)]; acc01 = fma2(packdup(f.x), qa.x, acc01); acc23 = fma2(packdup(f.x), qa.y, acc23);
                qa = qt2[2*(db+5)]; acc01 = fma2(packdup(f.y), qa.x, acc01); acc23 = fma2(packdup(f.y), qa.y, acc23);
                f = h2f(e.w);
                qa = qt2[2*(db+6)]; acc01 = fma2(packdup(f.x), qa.x, acc01); acc23 = fma2(packdup(f.x), qa.y, acc23);
                qa = qt2[2*(db+7)]; acc01 = fma2(packdup(f.y), qa.x, acc01); acc23 = fma2(packdup(f.y), qa.y, acc23);
            }
            if (c == 1) {
                int row = (idx >> 1) * 256 + r;
                if (row < NN) {
                    int mk = mkB[row];
                    float2 p01 = unpack2(acc01), p23 = unpack2(acc23);
                    int hb = q4 * 4;
                    s_compat[(hb + 0) * NN + row] = mk ? NEGV : p01.x;
                    s_compat[(hb + 1) * NN + row] = mk ? NEGV : p01.y;
                    s_compat[(hb + 2) * NN + row] = mk ? NEGV : p23.x;
                    s_compat[(hb + 3) * NN + row] = mk ? NEGV : p23.y;
                }
                acc01 = 0; acc23 = 0;
            }
        }
    }
    __syncthreads();

    // ---- Phase 1b: per-head softmax, 2 warps per head ----
    {
        int h = warp >> 1, seg = warp & 1;
        const float* row = s_compat + h * NN;
        float mx = -1e30f;
        for (int n = seg * 32 + lane; n < NN; n += 64) mx = fmaxf(mx, row[n]);
        #pragma unroll
        for (int o = 16; o > 0; o >>= 1) mx = fmaxf(mx, __shfl_xor_sync(~0u, mx, o));
        if (lane == 0) s_red[warp] = mx;
        __syncthreads();
        float hm = fmaxf(s_red[2 * h], s_red[2 * h + 1]);
        float sme = 0.f;
        for (int n = seg * 32 + lane; n < NN; n += 64) sme += __expf(row[n] - hm);
        #pragma unroll
        for (int o = 16; o > 0; o >>= 1) sme += __shfl_xor_sync(~0u, sme, o);
        if (lane == 0) s_red[16 + warp] = sme;
        __syncthreads();
        float inv = 1.0f / (s_red[16 + 2 * h] + s_red[16 + 2 * h + 1]);
        for (int n = seg * 32 + lane; n < NN; n += 64)
            s_buf[n * 8 + h] = __expf(row[n] - hm) * inv;   // s_at[n][8]
    }
    __syncthreads();

    // ---- Phase 2: ebar from fp16 scalar loads, MLP=8 ----
    {
        int dim = t & 127, g = t >> 7;
        const __half* Eh = (const __half*)e16B + dim;
        u64 a0 = 0, a1 = 0, a2 = 0, a3 = 0;
        int n = g;
        for (; n + 28 < NN; n += 32) {
            float e0 = __half2float(Eh[(size_t)n * 128]);
            float e1 = __half2float(Eh[(size_t)(n + 4) * 128]);
            float e2 = __half2float(Eh[(size_t)(n + 8) * 128]);
            float e3 = __half2float(Eh[(size_t)(n + 12) * 128]);
            float e4 = __half2float(Eh[(size_t)(n + 16) * 128]);
            float e5 = __half2float(Eh[(size_t)(n + 20) * 128]);
            float e6 = __half2float(Eh[(size_t)(n + 24) * 128]);
            float e7 = __half2float(Eh[(size_t)(n + 28) * 128]);
            const u64* t0 = (const u64*)(s_buf + n * 8);
            const u64* t1 = (const u64*)(s_buf + (n + 4) * 8);
            const u64* t2 = (const u64*)(s_buf + (n + 8) * 8);
            const u64* t3 = (const u64*)(s_buf + (n + 12) * 8);
            const u64* t4 = (const u64*)(s_buf + (n + 16) * 8);
            const u64* t5 = (const u64*)(s_buf + (n + 20) * 8);
            const u64* t6 = (const u64*)(s_buf + (n + 24) * 8);
            const u64* t7 = (const u64*)(s_buf + (n + 28) * 8);
            u64 d0 = packdup(e0), d1 = packdup(e1), d2 = packdup(e2), d3 = packdup(e3);
            a0 = fma2(d0, t0[0], a0); a1 = fma2(d0, t0[1], a1);
            a2 = fma2(d0, t0[2], a2); a3 = fma2(d0, t0[3], a3);
            a0 = fma2(d1, t1[0], a0); a1 = fma2(d1, t1[1], a1);
            a2 = fma2(d1, t1[2], a2); a3 = fma2(d1, t1[3], a3);
            a0 = fma2(d2, t2[0], a0); a1 = fma2(d2, t2[1], a1);
            a2 = fma2(d2, t2[2], a2); a3 = fma2(d2, t2[3], a3);
            a0 = fma2(d3, t3[0], a0); a1 = fma2(d3, t3[1], a1);
            a2 = fma2(d3, t3[2], a2); a3 = fma2(d3, t3[3], a3);
            u64 d4 = packdup(e4), d5 = packdup(e5), d6 = packdup(e6), d7 = packdup(e7);
            a0 = fma2(d4, t4[0], a0); a1 = fma2(d4, t4[1], a1);
            a2 = fma2(d4, t4[2], a2); a3 = fma2(d4, t4[3], a3);
            a0 = fma2(d5, t5[0], a0); a1 = fma2(d5, t5[1], a1);
            a2 = fma2(d5, t5[2], a2); a3 = fma2(d5, t5[3], a3);
            a0 = fma2(d6, t6[0], a0); a1 = fma2(d6, t6[1], a1);
            a2 = fma2(d6, t6[2], a2); a3 = fma2(d6, t6[3], a3);
            a0 = fma2(d7, t7[0], a0); a1 = fma2(d7, t7[1], a1);
            a2 = fma2(d7, t7[2], a2); a3 = fma2(d7, t7[3], a3);
        }
        for (; n < NN; n += 4) {
            u64 ed = packdup(__half2float(Eh[(size_t)n * 128]));
            const u64* at = (const u64*)(s_buf + n * 8);
            a0 = fma2(ed, at[0], a0); a1 = fma2(ed, at[1], a1);
            a2 = fma2(ed, at[2], a2); a3 = fma2(ed, at[3], a3);
        }
        __syncthreads();       // all s_at reads done; s_buf free
        ld16(0);               // prefetch phase-3 chunk 0 (overlaps matvecs)
        float2 f0 = unpack2(a0), f1 = unpack2(a1), f2 = unpack2(a2), f3 = unpack2(a3);
        float* pp = s_compat + g * 1024 + dim;   // partials [g][h][128]
        pp[0] = f0.x; pp[128] = f0.y; pp[256] = f1.x; pp[384] = f1.y;
        pp[512] = f2.x; pp[640] = f2.y; pp[768] = f3.x; pp[896] = f3.y;
    }
    __syncthreads();
    {
        s_ebar[t] = (s_compat[t] + s_compat[1024 + t])
                  + (s_compat[2048 + t] + s_compat[3072 + t]);
        int i2 = t + 512;
        s_ebar[i2] = (s_compat[i2] + s_compat[1024 + i2])
                   + (s_compat[2048 + i2] + s_compat[3072 + i2]);
    }
    __syncthreads();

    // ---- Phase 2b: heads -> glimpse -> gtilde ----
    if (t < DD) {
        int h = t >> 4;
        const float* eb = s_ebar + h * DD;
        float acc = 0.f;
        #pragma unroll 4
        for (int d = 0; d < DD; d++) acc += eb[d] * Wn[d * 384 + 128 + t];
        s_heads[t] = acc;
    }
    __syncthreads();
    if (t < DD) {
        float acc = 0.f;
        #pragma unroll 4
        for (int i = 0; i < DD; i++) acc += s_heads[i] * Wo[i * DD + t];
        s_gl[t] = acc;
    }
    __syncthreads();
    if (t < DD) {
        const float* w = Wn + t * 384 + 256;
        float acc = 0.f;
        #pragma unroll 4
        for (int j = 0; j < DD; j++) acc += w[j] * s_gl[j];
        s_gt[t] = acc * 0.08838834764831845f;
    }
    __syncthreads();

    // ---- Phase 3: logits from fp16, 8 chunk-iters, 2 thr/row dim-split ----
    float* s_lg = s_compat;
    float lmax = -1e30f;
    {
        const int r = t >> 1, p = t & 1;
        u64 acc = 0;
        for (int idx = 0; idx < 8; idx++) {
            __syncthreads();
            st16();
            __syncthreads();
            if (idx < 7) ld16(idx + 1);
            const uint4* bp = (const uint4*)s_buf + r * 9 + p * 4;
            int c = idx & 1;
            const u64* gtp = (const u64*)s_gt + c * 32 + p * 16;
            #pragma unroll
            for (int j = 0; j < 4; j++) {
                uint4 e = bp[j];
                float2 f0 = h2f(e.x), f1 = h2f(e.y), f2 = h2f(e.z), f3 = h2f(e.w);
                acc = fma2(pack2(f0.x, f0.y), gtp[j * 4 + 0], acc);
                acc = fma2(pack2(f1.x, f1.y), gtp[j * 4 + 1], acc);
                acc = fma2(pack2(f2.x, f2.y), gtp[j * 4 + 2], acc);
                acc = fma2(pack2(f3.x, f3.y), gtp[j * 4 + 3], acc);
            }
            if (c == 1) {
                float2 v = unpack2(acc);
                float s = v.x + v.y;
                s += __shfl_xor_sync(~0u, s, 1);
                int row = (idx >> 1) * 256 + r;
                if (p == 0 && row < NN) {
                    float vv = tanh_fast(s) * 10.0f;
                    if (mkB[row] != 0) vv = NEGV;
                    s_lg[row] = vv;
                    lmax = fmaxf(lmax, vv);
                }
                acc = 0;
            }
        }
    }
    __syncthreads();
    // ---- log-softmax over 1000 ----
    #pragma unroll
    for (int o = 16; o > 0; o >>= 1) lmax = fmaxf(lmax, __shfl_xor_sync(~0u, lmax, o));
    if (lane == 0) s_red[warp] = lmax;
    __syncthreads();
    float bmax = s_red[0];
    #pragma unroll
    for (int w = 1; w < 16; w++) bmax = fmaxf(bmax, s_red[w]);
    float ls = 0.f;
    for (int n = t; n < NN; n += 512) ls += __expf(s_lg[n] - bmax);
    #pragma unroll
    for (int o = 16; o > 0; o >>= 1) ls += __shfl_xor_sync(~0u, ls, o);
    if (lane == 0) s_red[16 + warp] = ls;
    __syncthreads();
    float tot = s_red[16];
    #pragma unroll
    for (int w = 1; w < 16; w++) tot += s_red[16 + w];
    float logZ = bmax + logf(tot);
    float* outB = out + (size_t)b * NN;
    for (int n = t; n < NN; n += 512) outB[n] = s_lg[n] - logZ;
}

extern "C" void kernel_launch(void* const* d_in, const int* in_sizes, int n_in,
                              void* d_out, int out_size) {
    const float* emb = (const float*)d_in[0];
    const float* Wn  = (const float*)d_in[1];
    const float* Wf  = (const float*)d_in[2];
    const float* Ws  = (const float*)d_in[3];
    const float* Wo  = (const float*)d_in[4];
    const int* fidx  = (const int*)d_in[5];
    const int* lidx  = (const int*)d_in[6];
    const int* mask  = (const int*)d_in[7];
    float* out = (float*)d_out;
    cudaFuncSetAttribute(attn_v7, cudaFuncAttributeMaxDynamicSharedMemorySize, SM_WORDS * 4);
    attn_v7<<<256, 512, SM_WORDS * 4>>>(emb, Wn, Wf, Ws, Wo, fidx, lidx, mask, out);
}